// round 2
// baseline (speedup 1.0000x reference)
#include <cuda_runtime.h>
#include <cuda_bf16.h>

// ---------------------------------------------------------------------------
// RNN: h_t = tanh(X_t @ W_xh + b_h + h_{t-1} @ W_hh) ; y_t = h_t @ W_hq + b_q
// out = [outputs (T*B*O floats) | states (T*B*H floats)]
// T=512 B=64 I=512 H=1024 O=512
//
// Plan:
//   1) sgemm_bias: states <- X @ W_xh + b_h          (Xproj, in-place staging)
//   2) rnn_recurrence: persistent 128-CTA kernel, grid barrier per step,
//      W_hh column-slice in smem, f32x2 packed FMA, in-place xp -> h.
//   3) sgemm_bias: outputs <- states @ W_hq + b_q
// ---------------------------------------------------------------------------

#define RT 512
#define RB 64
#define RH 1024
#define RI 512
#define RO 512
#define RNCTA 128
#define RCOLS 8

__device__ unsigned g_bar_count;

// ---- f32x2 packed math helpers (Blackwell dual-fp32 pipe) ----
__device__ __forceinline__ unsigned long long ffma2(unsigned long long a,
                                                    unsigned long long b,
                                                    unsigned long long c) {
    unsigned long long d;
    asm("fma.rn.f32x2 %0, %1, %2, %3;" : "=l"(d) : "l"(a), "l"(b), "l"(c));
    return d;
}
__device__ __forceinline__ unsigned long long pack2(float lo, float hi) {
    unsigned long long r;
    asm("mov.b64 %0, {%1, %2};" : "=l"(r) : "f"(lo), "f"(hi));
    return r;
}
__device__ __forceinline__ float2 unpack2(unsigned long long v) {
    float lo, hi;
    asm("mov.b64 {%0, %1}, %2;" : "=f"(lo), "=f"(hi) : "l"(v));
    return make_float2(lo, hi);
}

// ---------------------------------------------------------------------------
// Generic fp32 GEMM + bias: C[M,N] = A[M,K] @ B[K,N] + bias[N]
// BM=BN=128, BK=16, 256 threads, 8x8 per thread, f32x2 accumulation.
// All dims divisible by tiles for this problem (no bounds checks).
// ---------------------------------------------------------------------------
#define GBM 128
#define GBN 128
#define GBK 16

__global__ __launch_bounds__(256) void sgemm_bias(
    const float* __restrict__ A, const float* __restrict__ B,
    const float* __restrict__ bias, float* __restrict__ C,
    int M, int N, int K, int reset_bar)
{
    if (reset_bar && blockIdx.x == 0 && blockIdx.y == 0 && threadIdx.x == 0)
        g_bar_count = 0u;

    __shared__ __align__(16) float As[GBK][GBM + 4];
    __shared__ __align__(16) float Bs[GBK][GBN];

    const int tid = threadIdx.x;
    const int m0 = blockIdx.y * GBM;
    const int n0 = blockIdx.x * GBN;
    const int tm = tid >> 4;   // 0..15
    const int tn = tid & 15;   // 0..15

    unsigned long long acc[8][4];
#pragma unroll
    for (int i = 0; i < 8; i++)
#pragma unroll
        for (int j = 0; j < 4; j++) acc[i][j] = 0ull;

    const int arow = tid >> 2;   // 0..63
    const int acol4 = tid & 3;   // 0..3 (float4 index over BK=16)
    const int brow = tid >> 5;   // 0..7
    const int bcol4 = tid & 31;  // 0..31 (float4 index over BN=128)

    for (int k0 = 0; k0 < K; k0 += GBK) {
        // Load A tile (transposed into smem: As[k][m])
#pragma unroll
        for (int p = 0; p < 2; p++) {
            int r = arow + p * 64;
            float4 v = *(const float4*)(A + (size_t)(m0 + r) * K + k0 + acol4 * 4);
            As[acol4 * 4 + 0][r] = v.x;
            As[acol4 * 4 + 1][r] = v.y;
            As[acol4 * 4 + 2][r] = v.z;
            As[acol4 * 4 + 3][r] = v.w;
        }
        // Load B tile (natural layout Bs[k][n])
#pragma unroll
        for (int p = 0; p < 2; p++) {
            int r = brow + p * 8;
            float4 v = *(const float4*)(B + (size_t)(k0 + r) * N + n0 + bcol4 * 4);
            *(float4*)&Bs[r][bcol4 * 4] = v;
        }
        __syncthreads();

#pragma unroll
        for (int kk = 0; kk < GBK; kk++) {
            float4 a0 = *(const float4*)&As[kk][tm * 8];
            float4 a1 = *(const float4*)&As[kk][tm * 8 + 4];
            ulonglong2 b0 = *(const ulonglong2*)&Bs[kk][tn * 8];
            ulonglong2 b1 = *(const ulonglong2*)&Bs[kk][tn * 8 + 4];
            float av[8] = {a0.x, a0.y, a0.z, a0.w, a1.x, a1.y, a1.z, a1.w};
            unsigned long long bv[4] = {b0.x, b0.y, b1.x, b1.y};
#pragma unroll
            for (int i = 0; i < 8; i++) {
                unsigned long long aa = pack2(av[i], av[i]);
#pragma unroll
                for (int j = 0; j < 4; j++) acc[i][j] = ffma2(aa, bv[j], acc[i][j]);
            }
        }
        __syncthreads();
    }

    // Epilogue: add bias, store
    float bx[8];
#pragma unroll
    for (int c = 0; c < 8; c++) bx[c] = bias[n0 + tn * 8 + c];

#pragma unroll
    for (int i = 0; i < 8; i++) {
        float* cp = C + (size_t)(m0 + tm * 8 + i) * N + n0 + tn * 8;
        float2 v0 = unpack2(acc[i][0]);
        float2 v1 = unpack2(acc[i][1]);
        float2 v2 = unpack2(acc[i][2]);
        float2 v3 = unpack2(acc[i][3]);
        float4 o0 = make_float4(v0.x + bx[0], v0.y + bx[1], v1.x + bx[2], v1.y + bx[3]);
        float4 o1 = make_float4(v2.x + bx[4], v2.y + bx[5], v3.x + bx[6], v3.y + bx[7]);
        *(float4*)cp = o0;
        *(float4*)(cp + 4) = o1;
    }
}

// ---------------------------------------------------------------------------
// Recurrence: persistent kernel. 128 CTAs x 128 threads.
// CTA owns 8 columns of H; W_hh[:, n0:n0+8] cached in smem (32KB) as Ws[k][8].
// Thread t: b = t&63, j0 = (t>>6)*4 -> 4 output columns via 2 f32x2 accums.
// states[] doubles as Xproj input (in-place overwrite by owning thread).
// Grid barrier: monotonic atomic counter (reset by sgemm #1 each launch).
// ---------------------------------------------------------------------------
__global__ __launch_bounds__(128) void rnn_recurrence(
    const float* __restrict__ W_hh, float* __restrict__ states)
{
    __shared__ __align__(16) float Ws[RH][RCOLS];

    const int tid = threadIdx.x;
    const int n0 = blockIdx.x * RCOLS;

    // Preload W_hh column slice (one-time, reused for all 512 steps)
    for (int idx = tid; idx < RH * RCOLS; idx += 128) {
        int k = idx >> 3, j = idx & 7;
        Ws[k][j] = W_hh[(size_t)k * RH + n0 + j];
    }
    __syncthreads();

    const int b = tid & 63;
    const int j0 = (tid >> 6) * 4;

    for (int t = 0; t < RT; ++t) {
        unsigned long long acc0 = 0ull, acc1 = 0ull;
        if (t > 0) {
            const float* hp = states + (size_t)(t - 1) * (RB * RH) + (size_t)b * RH;
#pragma unroll 8
            for (int k = 0; k < RH; k += 4) {
                float4 h4 = *(const float4*)(hp + k);
                ulonglong2 w0 = *(const ulonglong2*)&Ws[k + 0][j0];
                ulonglong2 w1 = *(const ulonglong2*)&Ws[k + 1][j0];
                ulonglong2 w2 = *(const ulonglong2*)&Ws[k + 2][j0];
                ulonglong2 w3 = *(const ulonglong2*)&Ws[k + 3][j0];
                unsigned long long hx = pack2(h4.x, h4.x);
                acc0 = ffma2(hx, w0.x, acc0);
                acc1 = ffma2(hx, w0.y, acc1);
                unsigned long long hy = pack2(h4.y, h4.y);
                acc0 = ffma2(hy, w1.x, acc0);
                acc1 = ffma2(hy, w1.y, acc1);
                unsigned long long hz = pack2(h4.z, h4.z);
                acc0 = ffma2(hz, w2.x, acc0);
                acc1 = ffma2(hz, w2.y, acc1);
                unsigned long long hw = pack2(h4.w, h4.w);
                acc0 = ffma2(hw, w3.x, acc0);
                acc1 = ffma2(hw, w3.y, acc1);
            }
        }

        // Epilogue: h = tanh(xp + acc); in-place (same thread reads & writes)
        float* op = states + (size_t)t * (RB * RH) + (size_t)b * RH + n0 + j0;
        float4 xp = *(float4*)op;
        float2 a0 = unpack2(acc0);
        float2 a1 = unpack2(acc1);
        float4 hv;
        hv.x = tanhf(xp.x + a0.x);
        hv.y = tanhf(xp.y + a0.y);
        hv.z = tanhf(xp.z + a1.x);
        hv.w = tanhf(xp.w + a1.y);
        *(float4*)op = hv;

        // Grid barrier (all 128 CTAs resident by construction)
        __threadfence();
        __syncthreads();
        if (tid == 0) {
            atomicAdd(&g_bar_count, 1u);
            const unsigned tgt = (unsigned)RNCTA * (unsigned)(t + 1);
            while (*(volatile unsigned*)&g_bar_count < tgt) {}
        }
        __syncthreads();
    }
}

// ---------------------------------------------------------------------------
extern "C" void kernel_launch(void* const* d_in, const int* in_sizes, int n_in,
                              void* d_out, int out_size)
{
    const float* X    = (const float*)d_in[0];
    const float* W_xh = (const float*)d_in[1];
    const float* W_hh = (const float*)d_in[2];
    const float* b_h  = (const float*)d_in[3];
    const float* W_hq = (const float*)d_in[4];
    const float* b_q  = (const float*)d_in[5];

    float* outputs = (float*)d_out;                         // [T*B, O]
    float* states  = outputs + (size_t)RT * RB * RO;        // [T*B, H]

    const int M = RT * RB;  // 32768

    dim3 blk(256);
    dim3 g1(RH / GBN, M / GBM);   // Xproj: N=1024, K=512
    sgemm_bias<<<g1, blk>>>(X, W_xh, b_h, states, M, RH, RI, 1);

    rnn_recurrence<<<RNCTA, 128>>>(W_hh, states);

    dim3 g3(RO / GBN, M / GBM);   // outputs: N=512, K=1024
    sgemm_bias<<<g3, blk>>>(states, W_hq, b_q, outputs, M, RO, RH, 0);
}

// round 3
// speedup vs baseline: 1.8861x; 1.8861x over previous
#include <cuda_runtime.h>
#include <cuda_bf16.h>

// ---------------------------------------------------------------------------
// RNN: h_t = tanh(X_t @ W_xh + b_h + h_{t-1} @ W_hh) ; y_t = h_t @ W_hq + b_q
// out = [outputs (T*B*O floats) | states (T*B*H floats)]
// T=512 B=64 I=512 H=1024 O=512
//
// R2: recurrence rebuilt — coalesced smem staging of h (kills the 32-line
// uncoalesced LDG wavefront storm seen in R1), transposed W in smem,
// f32x2 FMA from (k,k+1) pairs, 256 threads with k-split + pair reduction.
// ---------------------------------------------------------------------------

#define RT 512
#define RB 64
#define RH 1024
#define RI 512
#define RO 512
#define RNCTA 128
#define RCOLS 8
#define CHUNK 128
#define NCHUNK 8
#define HS_STRIDE 132   // 33 x 16B: odd in float4 units -> conflict-free LDS.128

__device__ unsigned g_bar_count;

// ---- f32x2 packed math helpers (Blackwell dual-fp32 pipe) ----
__device__ __forceinline__ unsigned long long ffma2(unsigned long long a,
                                                    unsigned long long b,
                                                    unsigned long long c) {
    unsigned long long d;
    asm("fma.rn.f32x2 %0, %1, %2, %3;" : "=l"(d) : "l"(a), "l"(b), "l"(c));
    return d;
}
__device__ __forceinline__ unsigned long long pack2(float lo, float hi) {
    unsigned long long r;
    asm("mov.b64 %0, {%1, %2};" : "=l"(r) : "f"(lo), "f"(hi));
    return r;
}
__device__ __forceinline__ float2 unpack2(unsigned long long v) {
    float lo, hi;
    asm("mov.b64 {%0, %1}, %2;" : "=f"(lo), "=f"(hi) : "l"(v));
    return make_float2(lo, hi);
}
__device__ __forceinline__ float4 ldcv4(const float* p) {
    float4 v;
    asm volatile("ld.global.cv.v4.f32 {%0,%1,%2,%3}, [%4];"
                 : "=f"(v.x), "=f"(v.y), "=f"(v.z), "=f"(v.w) : "l"(p));
    return v;
}

// ---------------------------------------------------------------------------
// Generic fp32 GEMM + bias: C[M,N] = A[M,K] @ B[K,N] + bias[N]  (unchanged R1)
// ---------------------------------------------------------------------------
#define GBM 128
#define GBN 128
#define GBK 16

__global__ __launch_bounds__(256) void sgemm_bias(
    const float* __restrict__ A, const float* __restrict__ B,
    const float* __restrict__ bias, float* __restrict__ C,
    int M, int N, int K, int reset_bar)
{
    if (reset_bar && blockIdx.x == 0 && blockIdx.y == 0 && threadIdx.x == 0)
        g_bar_count = 0u;

    __shared__ __align__(16) float As[GBK][GBM + 4];
    __shared__ __align__(16) float Bs[GBK][GBN];

    const int tid = threadIdx.x;
    const int m0 = blockIdx.y * GBM;
    const int n0 = blockIdx.x * GBN;
    const int tm = tid >> 4;
    const int tn = tid & 15;

    unsigned long long acc[8][4];
#pragma unroll
    for (int i = 0; i < 8; i++)
#pragma unroll
        for (int j = 0; j < 4; j++) acc[i][j] = 0ull;

    const int arow = tid >> 2;
    const int acol4 = tid & 3;
    const int brow = tid >> 5;
    const int bcol4 = tid & 31;

    for (int k0 = 0; k0 < K; k0 += GBK) {
#pragma unroll
        for (int p = 0; p < 2; p++) {
            int r = arow + p * 64;
            float4 v = *(const float4*)(A + (size_t)(m0 + r) * K + k0 + acol4 * 4);
            As[acol4 * 4 + 0][r] = v.x;
            As[acol4 * 4 + 1][r] = v.y;
            As[acol4 * 4 + 2][r] = v.z;
            As[acol4 * 4 + 3][r] = v.w;
        }
#pragma unroll
        for (int p = 0; p < 2; p++) {
            int r = brow + p * 8;
            float4 v = *(const float4*)(B + (size_t)(k0 + r) * N + n0 + bcol4 * 4);
            *(float4*)&Bs[r][bcol4 * 4] = v;
        }
        __syncthreads();

#pragma unroll
        for (int kk = 0; kk < GBK; kk++) {
            float4 a0 = *(const float4*)&As[kk][tm * 8];
            float4 a1 = *(const float4*)&As[kk][tm * 8 + 4];
            ulonglong2 b0 = *(const ulonglong2*)&Bs[kk][tn * 8];
            ulonglong2 b1 = *(const ulonglong2*)&Bs[kk][tn * 8 + 4];
            float av[8] = {a0.x, a0.y, a0.z, a0.w, a1.x, a1.y, a1.z, a1.w};
            unsigned long long bv[4] = {b0.x, b0.y, b1.x, b1.y};
#pragma unroll
            for (int i = 0; i < 8; i++) {
                unsigned long long aa = pack2(av[i], av[i]);
#pragma unroll
                for (int j = 0; j < 4; j++) acc[i][j] = ffma2(aa, bv[j], acc[i][j]);
            }
        }
        __syncthreads();
    }

    float bx[8];
#pragma unroll
    for (int c = 0; c < 8; c++) bx[c] = bias[n0 + tn * 8 + c];

#pragma unroll
    for (int i = 0; i < 8; i++) {
        float* cp = C + (size_t)(m0 + tm * 8 + i) * N + n0 + tn * 8;
        float2 v0 = unpack2(acc[i][0]);
        float2 v1 = unpack2(acc[i][1]);
        float2 v2 = unpack2(acc[i][2]);
        float2 v3 = unpack2(acc[i][3]);
        float4 o0 = make_float4(v0.x + bx[0], v0.y + bx[1], v1.x + bx[2], v1.y + bx[3]);
        float4 o1 = make_float4(v2.x + bx[4], v2.y + bx[5], v3.x + bx[6], v3.y + bx[7]);
        *(float4*)cp = o0;
        *(float4*)(cp + 4) = o1;
    }
}

// ---------------------------------------------------------------------------
// Recurrence v2. 128 CTAs x 256 threads, persistent, grid barrier per step.
// CTA owns 8 H-columns. Smem: Wt[8][1024] (transposed W slice, loaded once),
// Hs[64][132] chunk buffer, Red[128][4] reduction pad.
// Thread: b = tid&63, jp = (tid>>6)&1 (4 cols), kh = tid>>7 (k half).
// ---------------------------------------------------------------------------
__device__ __forceinline__ void grid_bar(unsigned* epoch, int tid) {
    __threadfence();
    __syncthreads();
    *epoch += 1;
    if (tid == 0) {
        atomicAdd(&g_bar_count, 1u);
        const unsigned tgt = (*epoch) * (unsigned)RNCTA;
        while (*(volatile unsigned*)&g_bar_count < tgt) {}
    }
    __syncthreads();
}

__global__ __launch_bounds__(256) void rnn_recurrence(
    const float* __restrict__ W_hh, float* __restrict__ states)
{
    extern __shared__ float sm[];
    float* Wt  = sm;                       // 8*1024 = 8192 floats
    float* Hs  = sm + RCOLS * RH;          // 64*132 = 8448 floats
    float* Red = Hs + RB * HS_STRIDE;      // 128*4  = 512 floats

    const int tid = threadIdx.x;
    const int n0 = blockIdx.x * RCOLS;
    const int b  = tid & 63;
    const int jp = (tid >> 6) & 1;
    const int kh = tid >> 7;
    const int w32 = tid >> 5;     // warp id 0..7 (chunk-load row base)
    const int c4  = tid & 31;     // float4 column within chunk row

    // One-time: transpose W_hh column slice into smem Wt[j][k]
    for (int idx = tid; idx < RCOLS * RH; idx += 256) {
        int j = idx & 7, k = idx >> 3;
        Wt[j * RH + k] = W_hh[(size_t)k * RH + n0 + j];
    }
    __syncthreads();

    unsigned epoch = 0;

    // t = 0: h_0 = tanh(xp)   (kh==0 threads cover all 512 outputs of this CTA)
    if (kh == 0) {
        float* op = states + (size_t)b * RH + n0 + jp * 4;
        float4 xp = *(float4*)op;
        float4 hv;
        hv.x = tanhf(xp.x); hv.y = tanhf(xp.y);
        hv.z = tanhf(xp.z); hv.w = tanhf(xp.w);
        *(float4*)op = hv;
    }
    grid_bar(&epoch, tid);

    const float* hsp = Hs + b * HS_STRIDE + kh * 64;       // this thread's h slice
    const float* wtp = Wt + (jp * 4) * RH + kh * 64;       // this thread's W cols

    for (int t = 1; t < RT; ++t) {
        const float* hprev = states + (size_t)(t - 1) * (RB * RH);

        // prologue: LDG chunk 0 into registers (coalesced, L1-bypass)
        float4 stage[8];
#pragma unroll
        for (int i = 0; i < 8; i++)
            stage[i] = ldcv4(hprev + (size_t)(w32 + 8 * i) * RH + c4 * 4);

        unsigned long long a0 = 0ull, a1 = 0ull, a2 = 0ull, a3 = 0ull;

        for (int c = 0; c < NCHUNK; ++c) {
            // commit staged chunk c to smem
#pragma unroll
            for (int i = 0; i < 8; i++)
                *(float4*)(Hs + (w32 + 8 * i) * HS_STRIDE + c4 * 4) = stage[i];
            __syncthreads();

            // prefetch chunk c+1 (retires during compute below)
            if (c + 1 < NCHUNK) {
                const float* gsrc = hprev + (c + 1) * CHUNK;
#pragma unroll
                for (int i = 0; i < 8; i++)
                    stage[i] = ldcv4(gsrc + (size_t)(w32 + 8 * i) * RH + c4 * 4);
            }

            // compute: 64 k-values x 4 columns from smem
            const float* wc = wtp + c * CHUNK;
#pragma unroll
            for (int i = 0; i < 16; i++) {
                ulonglong2 h2 = *(const ulonglong2*)(hsp + i * 4);
                ulonglong2 w0 = *(const ulonglong2*)(wc + 0 * RH + i * 4);
                ulonglong2 w1 = *(const ulonglong2*)(wc + 1 * RH + i * 4);
                ulonglong2 w2 = *(const ulonglong2*)(wc + 2 * RH + i * 4);
                ulonglong2 w3 = *(const ulonglong2*)(wc + 3 * RH + i * 4);
                a0 = ffma2(h2.x, w0.x, a0); a0 = ffma2(h2.y, w0.y, a0);
                a1 = ffma2(h2.x, w1.x, a1); a1 = ffma2(h2.y, w1.y, a1);
                a2 = ffma2(h2.x, w2.x, a2); a2 = ffma2(h2.y, w2.y, a2);
                a3 = ffma2(h2.x, w3.x, a3); a3 = ffma2(h2.y, w3.y, a3);
            }
            __syncthreads();
        }

        // fold f32x2 halves -> 4 partial column sums
        float2 f0 = unpack2(a0), f1 = unpack2(a1), f2 = unpack2(a2), f3 = unpack2(a3);
        float4 part = make_float4(f0.x + f0.y, f1.x + f1.y, f2.x + f2.y, f3.x + f3.y);

        // pair-reduce the two k-halves, then epilogue
        if (kh == 1) *(float4*)(Red + (tid - 128) * 4) = part;
        __syncthreads();
        if (kh == 0) {
            float4 oth = *(const float4*)(Red + tid * 4);
            float* op = states + (size_t)t * (RB * RH) + (size_t)b * RH + n0 + jp * 4;
            float4 xp = *(float4*)op;
            float4 hv;
            hv.x = tanhf(xp.x + part.x + oth.x);
            hv.y = tanhf(xp.y + part.y + oth.y);
            hv.z = tanhf(xp.z + part.z + oth.z);
            hv.w = tanhf(xp.w + part.w + oth.w);
            *(float4*)op = hv;
        }

        grid_bar(&epoch, tid);
    }
}

// ---------------------------------------------------------------------------
extern "C" void kernel_launch(void* const* d_in, const int* in_sizes, int n_in,
                              void* d_out, int out_size)
{
    const float* X    = (const float*)d_in[0];
    const float* W_xh = (const float*)d_in[1];
    const float* W_hh = (const float*)d_in[2];
    const float* b_h  = (const float*)d_in[3];
    const float* W_hq = (const float*)d_in[4];
    const float* b_q  = (const float*)d_in[5];

    float* outputs = (float*)d_out;                      // [T*B, O]
    float* states  = outputs + (size_t)RT * RB * RO;     // [T*B, H]

    const int M = RT * RB;  // 32768
    const int rec_smem = (RCOLS * RH + RB * HS_STRIDE + 128 * 4) * (int)sizeof(float);

    cudaFuncSetAttribute(rnn_recurrence,
                         cudaFuncAttributeMaxDynamicSharedMemorySize, rec_smem);

    dim3 blk(256);
    dim3 g1(RH / GBN, M / GBM);   // Xproj: N=1024, K=512 (resets barrier ctr)
    sgemm_bias<<<g1, blk>>>(X, W_xh, b_h, states, M, RH, RI, 1);

    rnn_recurrence<<<RNCTA, 256, rec_smem>>>(W_hh, states);

    dim3 g3(RO / GBN, M / GBM);   // outputs: N=512, K=1024
    sgemm_bias<<<g3, blk>>>(states, W_hq, b_q, outputs, M, RO, RH, 0);
}